// round 3
// baseline (speedup 1.0000x reference)
#include <cuda_runtime.h>
#include <math.h>

#define BSZ     4
#define SEQ     512
#define HID     1024
#define M_TOT   2048        // BSZ*SEQ
#define NPROJ   6400        // 256 + 3072 + 3072
#define NHEADS  50          // 2 ent + 24 head + 24 tail

// Scratch (allocation-free rule: __device__ globals)
__device__ float g_proj[(size_t)M_TOT * NPROJ];          // 52.4 MB
__device__ float g_q[(size_t)BSZ * NHEADS * SEQ * 64];   // 26.2 MB
__device__ float g_k[(size_t)BSZ * NHEADS * SEQ * 64];   // 26.2 MB

// ---------------------------------------------------------------------------
// GEMM1: proj = x @ W + b   (M=2048, N=ldb columns, K=1024)
// 128x128 block tile, BK=16, 256 threads, 8x8 microtile.
// ---------------------------------------------------------------------------
__global__ __launch_bounds__(256) void gemm_proj(
    const float* __restrict__ A, const float* __restrict__ W,
    const float* __restrict__ bias, int ldb, int colOff)
{
    __shared__ float As[16][132];
    __shared__ float Bs[16][132];
    const int t  = threadIdx.x;
    const int m0 = blockIdx.y * 128;
    const int n0 = blockIdx.x * 128;
    const int ty = t >> 4, tx = t & 15;

    float acc[8][8];
#pragma unroll
    for (int i = 0; i < 8; ++i)
#pragma unroll
        for (int j = 0; j < 8; ++j) acc[i][j] = 0.f;

    for (int k0 = 0; k0 < HID; k0 += 16) {
#pragma unroll
        for (int it = 0; it < 2; ++it) {
            int idx = t + it * 256;
            int r   = idx >> 2;          // 0..127
            int c4  = (idx & 3) << 2;    // 0,4,8,12
            float4 av = *reinterpret_cast<const float4*>(
                &A[(size_t)(m0 + r) * HID + k0 + c4]);
            As[c4 + 0][r] = av.x; As[c4 + 1][r] = av.y;
            As[c4 + 2][r] = av.z; As[c4 + 3][r] = av.w;
            int br = idx >> 5;           // 0..15
            int bc = (idx & 31) << 2;    // 0..124
            *reinterpret_cast<float4*>(&Bs[br][bc]) =
                *reinterpret_cast<const float4*>(&W[(size_t)(k0 + br) * ldb + n0 + bc]);
        }
        __syncthreads();
#pragma unroll
        for (int kk = 0; kk < 16; ++kk) {
            float a[8], bb[8];
            *reinterpret_cast<float4*>(&a[0])  = *reinterpret_cast<float4*>(&As[kk][ty * 8]);
            *reinterpret_cast<float4*>(&a[4])  = *reinterpret_cast<float4*>(&As[kk][ty * 8 + 4]);
            *reinterpret_cast<float4*>(&bb[0]) = *reinterpret_cast<float4*>(&Bs[kk][tx * 8]);
            *reinterpret_cast<float4*>(&bb[4]) = *reinterpret_cast<float4*>(&Bs[kk][tx * 8 + 4]);
#pragma unroll
            for (int i = 0; i < 8; ++i)
#pragma unroll
                for (int j = 0; j < 8; ++j)
                    acc[i][j] = fmaf(a[i], bb[j], acc[i][j]);
        }
        __syncthreads();
    }

    float bv[8];
#pragma unroll
    for (int j = 0; j < 8; ++j) bv[j] = bias[n0 + tx * 8 + j];
#pragma unroll
    for (int i = 0; i < 8; ++i) {
        int row = m0 + ty * 8 + i;
        float4 v0, v1;
        v0.x = acc[i][0] + bv[0]; v0.y = acc[i][1] + bv[1];
        v0.z = acc[i][2] + bv[2]; v0.w = acc[i][3] + bv[3];
        v1.x = acc[i][4] + bv[4]; v1.y = acc[i][5] + bv[5];
        v1.z = acc[i][6] + bv[6]; v1.w = acc[i][7] + bv[7];
        float* dst = &g_proj[(size_t)row * NPROJ + colOff + n0 + tx * 8];
        *reinterpret_cast<float4*>(dst)     = v0;
        *reinterpret_cast<float4*>(dst + 4) = v1;
    }
}

// ---------------------------------------------------------------------------
// RoPE 2D: read proj, rotate pairs, scatter into per-(b,head) q/k layout.
// grid = M_TOT*NHEADS blocks of 64 threads; thread = (qk, pair).
// cos width 64 = concat(cos(xp*div)[32], cos(yp*div)[32]); repeat-2 pairs
// share the same angle, freq index f = pair (or pair-16), div = 10000^(-f/16).
// ---------------------------------------------------------------------------
__global__ void rope_kernel(const int* __restrict__ xp, const int* __restrict__ yp)
{
    int blk  = blockIdx.x;               // m * NHEADS + head
    int m    = blk / NHEADS;
    int head = blk - m * NHEADS;
    int t    = threadIdx.x;              // 0..63
    int qk   = t >> 5;
    int i    = t & 31;

    float2 v = *reinterpret_cast<const float2*>(
        &g_proj[(size_t)m * NPROJ + head * 128 + qk * 64 + 2 * i]);

    int p = (i < 16) ? xp[m] : yp[m];
    int f = (i < 16) ? i : (i - 16);
    // div[f] = exp(-ln(10000)*f/16) = 2^(-f * log2(10000)/16)
    float ang = (float)p * exp2f(-0.83048202372184f * (float)f);
    float sn, cs;
    sincosf(ang, &sn, &cs);

    float2 r;
    r.x = v.x * cs - v.y * sn;
    r.y = v.y * cs + v.x * sn;

    int b = m >> 9, sidx = m & (SEQ - 1);
    float* dst = qk ? g_k : g_q;
    *reinterpret_cast<float2*>(
        &dst[((size_t)(b * NHEADS + head) * SEQ + sidx) * 64 + 2 * i]) = r;
}

// ---------------------------------------------------------------------------
// GEMM2: S = Q @ K^T per (b, head) + mask / tril / scale epilogue.
// grid (4, 4, 200): 128x128 tiles over the 512x512 logits, BK=16 (4 chunks).
// ---------------------------------------------------------------------------
__global__ __launch_bounds__(256) void attn_gemm(const int* __restrict__ amask,
                                                 float* __restrict__ out)
{
    __shared__ float Qs[16][132];
    __shared__ float Ks[16][132];
    const int t    = threadIdx.x;
    const int bh   = blockIdx.z;                // b * NHEADS + head
    const int b    = bh / NHEADS;
    const int head = bh - b * NHEADS;
    const int m0   = blockIdx.y * 128;
    const int n0   = blockIdx.x * 128;
    const float* Q = g_q + (size_t)bh * SEQ * 64;
    const float* K = g_k + (size_t)bh * SEQ * 64;
    const int ty = t >> 4, tx = t & 15;

    float acc[8][8];
#pragma unroll
    for (int i = 0; i < 8; ++i)
#pragma unroll
        for (int j = 0; j < 8; ++j) acc[i][j] = 0.f;

    for (int k0 = 0; k0 < 64; k0 += 16) {
#pragma unroll
        for (int it = 0; it < 2; ++it) {
            int idx = t + it * 256;
            int r   = idx >> 2;
            int c4  = (idx & 3) << 2;
            float4 qv = *reinterpret_cast<const float4*>(
                &Q[(size_t)(m0 + r) * 64 + k0 + c4]);
            Qs[c4 + 0][r] = qv.x; Qs[c4 + 1][r] = qv.y;
            Qs[c4 + 2][r] = qv.z; Qs[c4 + 3][r] = qv.w;
            float4 kv = *reinterpret_cast<const float4*>(
                &K[(size_t)(n0 + r) * 64 + k0 + c4]);
            Ks[c4 + 0][r] = kv.x; Ks[c4 + 1][r] = kv.y;
            Ks[c4 + 2][r] = kv.z; Ks[c4 + 3][r] = kv.w;
        }
        __syncthreads();
#pragma unroll
        for (int kk = 0; kk < 16; ++kk) {
            float a[8], bb[8];
            *reinterpret_cast<float4*>(&a[0])  = *reinterpret_cast<float4*>(&Qs[kk][ty * 8]);
            *reinterpret_cast<float4*>(&a[4])  = *reinterpret_cast<float4*>(&Qs[kk][ty * 8 + 4]);
            *reinterpret_cast<float4*>(&bb[0]) = *reinterpret_cast<float4*>(&Ks[kk][tx * 8]);
            *reinterpret_cast<float4*>(&bb[4]) = *reinterpret_cast<float4*>(&Ks[kk][tx * 8 + 4]);
#pragma unroll
            for (int i = 0; i < 8; ++i)
#pragma unroll
                for (int j = 0; j < 8; ++j)
                    acc[i][j] = fmaf(a[i], bb[j], acc[i][j]);
        }
        __syncthreads();
    }

    bool pm[8], pn[8];
#pragma unroll
    for (int i = 0; i < 8; ++i) pm[i] = amask[b * SEQ + m0 + ty * 8 + i] > 0;
#pragma unroll
    for (int j = 0; j < 8; ++j) pn[j] = amask[b * SEQ + n0 + tx * 8 + j] > 0;
    const bool ent = head < 2;

#pragma unroll
    for (int i = 0; i < 8; ++i) {
        int mrow = m0 + ty * 8 + i;
        float vals[8];
#pragma unroll
        for (int j = 0; j < 8; ++j) {
            int ncol = n0 + tx * 8 + j;
            float v = (pm[i] && pn[j]) ? acc[i][j] : -INFINITY;
            if (ent && mrow > ncol) v -= 1e12f;   // tril(-1) * NEG_BIG
            vals[j] = v * 0.125f;                 // / sqrt(64)
        }
        float* dst = &out[((size_t)bh * SEQ + mrow) * SEQ + n0 + tx * 8];
        *reinterpret_cast<float4*>(dst)     = *reinterpret_cast<float4*>(&vals[0]);
        *reinterpret_cast<float4*>(dst + 4) = *reinterpret_cast<float4*>(&vals[4]);
    }
}

// ---------------------------------------------------------------------------
extern "C" void kernel_launch(void* const* d_in, const int* in_sizes, int n_in,
                              void* d_out, int out_size)
{
    const float* x      = (const float*)d_in[0];
    const int*   amask  = (const int*)  d_in[1];
    const int*   xp     = (const int*)  d_in[2];
    const int*   yp     = (const int*)  d_in[3];
    const float* W_ent  = (const float*)d_in[4];
    const float* b_ent  = (const float*)d_in[5];
    const float* W_head = (const float*)d_in[6];
    const float* b_head = (const float*)d_in[7];
    const float* W_tail = (const float*)d_in[8];
    const float* b_tail = (const float*)d_in[9];
    float* out = (float*)d_out;

    gemm_proj<<<dim3( 2, 16), 256>>>(x, W_ent,  b_ent,   256,    0);
    gemm_proj<<<dim3(24, 16), 256>>>(x, W_head, b_head, 3072,  256);
    gemm_proj<<<dim3(24, 16), 256>>>(x, W_tail, b_tail, 3072, 3328);
    rope_kernel<<<M_TOT * NHEADS, 64>>>(xp, yp);
    attn_gemm<<<dim3(4, 4, BSZ * NHEADS), 256>>>(amask, out);
}

// round 5
// speedup vs baseline: 2.7940x; 2.7940x over previous
#include <cuda_runtime.h>
#include <cuda_bf16.h>
#include <cstdint>
#include <math.h>

#define BSZ     4
#define SEQ     512
#define HID     1024
#define M_TOT   2048
#define NPROJ   6400
#define NHEADS  50

// ---------------------------------------------------------------- scratch
__device__ float         g_proj[(size_t)M_TOT * NPROJ];
__device__ float         g_bias[NPROJ];
__device__ __nv_bfloat16 g_xh[(size_t)M_TOT * HID];
__device__ __nv_bfloat16 g_xl[(size_t)M_TOT * HID];
__device__ __nv_bfloat16 g_Wh[(size_t)NPROJ * HID];     // [n][k]
__device__ __nv_bfloat16 g_Wl[(size_t)NPROJ * HID];
__device__ __nv_bfloat16 g_qh[(size_t)BSZ * NHEADS * SEQ * 64];
__device__ __nv_bfloat16 g_ql[(size_t)BSZ * NHEADS * SEQ * 64];
__device__ __nv_bfloat16 g_kh[(size_t)BSZ * NHEADS * SEQ * 64];
__device__ __nv_bfloat16 g_kl[(size_t)BSZ * NHEADS * SEQ * 64];

// ---------------------------------------------------------------- helpers
__device__ __forceinline__ uint32_t smem_u32(const void* p) {
    uint32_t a;
    asm("{ .reg .u64 t; cvta.to.shared.u64 t, %1; cvt.u32.u64 %0, t; }" : "=r"(a) : "l"(p));
    return a;
}
__device__ __forceinline__ void cp16(uint32_t dst, const void* src) {
    asm volatile("cp.async.cg.shared.global [%0], [%1], 16;" :: "r"(dst), "l"(src));
}
#define CP_COMMIT() asm volatile("cp.async.commit_group;" ::: "memory")
#define CP_WAIT1()  asm volatile("cp.async.wait_group 1;" ::: "memory")

__device__ __forceinline__ void ldsm4(uint32_t* r, uint32_t a) {
    asm volatile("ldmatrix.sync.aligned.m8n8.x4.shared.b16 {%0,%1,%2,%3}, [%4];"
                 : "=r"(r[0]), "=r"(r[1]), "=r"(r[2]), "=r"(r[3]) : "r"(a));
}
__device__ __forceinline__ void mma16816(float* d, const uint32_t* a, const uint32_t* b) {
    asm volatile("mma.sync.aligned.m16n8k16.row.col.f32.bf16.bf16.f32 "
                 "{%0,%1,%2,%3}, {%4,%5,%6,%7}, {%8,%9}, {%0,%1,%2,%3};"
                 : "+f"(d[0]), "+f"(d[1]), "+f"(d[2]), "+f"(d[3])
                 : "r"(a[0]), "r"(a[1]), "r"(a[2]), "r"(a[3]), "r"(b[0]), "r"(b[1]));
}

// smem tile geometry: 128 rows x 16 bf16 (32B) + 16B pad = 48B stride
#define TSTRIDE 48
#define TILE_B  (128 * TSTRIDE)      // 6144
#define STAGE_B (4 * TILE_B)         // 24576 : Ah, Al, Bh, Bl

// load one stage (4 tiles) with cp.async; 256 threads, 16B each x 4 tiles
__device__ __forceinline__ void load_stage(
    uint32_t sb,
    const __nv_bfloat16* Ah, const __nv_bfloat16* Al,
    const __nv_bfloat16* Bh, const __nv_bfloat16* Bl,
    int m0, int n0, int lda, int ldb, int k0, int t)
{
    int row = t >> 1, half = t & 1;
    uint32_t d = sb + row * TSTRIDE + half * 16;
    size_t ao = (size_t)(m0 + row) * lda + k0 + half * 8;
    size_t bo = (size_t)(n0 + row) * ldb + k0 + half * 8;
    cp16(d,              Ah + ao);
    cp16(d + TILE_B,     Al + ao);
    cp16(d + 2 * TILE_B, Bh + bo);
    cp16(d + 3 * TILE_B, Bl + bo);
}

// one BK=16 compute step: 8 A-ldsm, 4 B-ldsm, 48 HMMA per warp
__device__ __forceinline__ void compute_stage(uint32_t sb, int wm, int wn, int lane,
                                              float acc[4][4][4])
{
    uint32_t Ah[4][4], Al[4][4], Bh[2][4], Bl[2][4];
    uint32_t aoff = (uint32_t)((wm * 64 + (lane & 15)) * TSTRIDE + ((lane >> 4) & 1) * 16);
#pragma unroll
    for (int mt = 0; mt < 4; ++mt) {
        uint32_t a = sb + mt * 16 * TSTRIDE + aoff;
        ldsm4(Ah[mt], a);
        ldsm4(Al[mt], a + TILE_B);
    }
    uint32_t boff = (uint32_t)((wn * 32 + (lane & 7) + ((lane >> 4) & 1) * 8) * TSTRIDE
                               + ((lane >> 3) & 1) * 16);
#pragma unroll
    for (int np = 0; np < 2; ++np) {
        uint32_t a = sb + 2 * TILE_B + np * 16 * TSTRIDE + boff;
        ldsm4(Bh[np], a);
        ldsm4(Bl[np], a + TILE_B);
    }
#pragma unroll
    for (int mt = 0; mt < 4; ++mt)
#pragma unroll
        for (int nt = 0; nt < 4; ++nt) {
            const uint32_t* bh = &Bh[nt >> 1][(nt & 1) * 2];
            const uint32_t* bl = &Bl[nt >> 1][(nt & 1) * 2];
            mma16816(acc[mt][nt], Ah[mt], bh);
            mma16816(acc[mt][nt], Ah[mt], bl);
            mma16816(acc[mt][nt], Al[mt], bh);
        }
}

// ---------------------------------------------------------------- conversions
__global__ __launch_bounds__(256) void conv_x(const float* __restrict__ x) {
    int i = blockIdx.x * 256 + threadIdx.x;
    float4 v = reinterpret_cast<const float4*>(x)[i];
    union { __nv_bfloat16 h[4]; uint2 u; } H, L;
    float f[4] = {v.x, v.y, v.z, v.w};
#pragma unroll
    for (int j = 0; j < 4; ++j) {
        H.h[j] = __float2bfloat16(f[j]);
        L.h[j] = __float2bfloat16(f[j] - __bfloat162float(H.h[j]));
    }
    reinterpret_cast<uint2*>(g_xh)[i] = H.u;
    reinterpret_cast<uint2*>(g_xl)[i] = L.u;
}

__global__ __launch_bounds__(1024) void conv_w(const float* __restrict__ W, int Nsec, int colOff) {
    __shared__ float tile[32][33];
    int n0 = blockIdx.x * 32, k0 = blockIdx.y * 32;
    int tx = threadIdx.x, ty = threadIdx.y;
    tile[ty][tx] = W[(size_t)(k0 + ty) * Nsec + n0 + tx];
    __syncthreads();
    float v = tile[tx][ty];
    __nv_bfloat16 h = __float2bfloat16(v);
    __nv_bfloat16 l = __float2bfloat16(v - __bfloat162float(h));
    size_t o = (size_t)(colOff + n0 + ty) * HID + k0 + tx;
    g_Wh[o] = h;  g_Wl[o] = l;
}

__global__ void conv_b(const float* __restrict__ be, const float* __restrict__ bh,
                       const float* __restrict__ bt) {
    int i = blockIdx.x * 256 + threadIdx.x;
    if (i < NPROJ)
        g_bias[i] = (i < 256) ? be[i] : (i < 3328) ? bh[i - 256] : bt[i - 3328];
}

// ---------------------------------------------------------------- proj GEMM
__global__ __launch_bounds__(256) void proj_mma() {
    __shared__ __align__(128) char smem[2 * STAGE_B];   // 49152
    uint32_t sb = smem_u32(smem);
    const int t = threadIdx.x, lane = t & 31, w = t >> 5;
    const int wm = w >> 2, wn = w & 3;
    const int n0 = blockIdx.x * 128, m0 = blockIdx.y * 128;

    float acc[4][4][4];
#pragma unroll
    for (int i = 0; i < 4; ++i)
#pragma unroll
        for (int j = 0; j < 4; ++j)
#pragma unroll
            for (int k = 0; k < 4; ++k) acc[i][j][k] = 0.f;

    load_stage(sb,           g_xh, g_xl, g_Wh, g_Wl, m0, n0, HID, HID, 0, t);
    CP_COMMIT();
    load_stage(sb + STAGE_B, g_xh, g_xl, g_Wh, g_Wl, m0, n0, HID, HID, 16, t);
    CP_COMMIT();

#pragma unroll 1
    for (int ks = 0; ks < 64; ++ks) {
        CP_WAIT1();
        __syncthreads();
        compute_stage(sb + (ks & 1) * STAGE_B, wm, wn, lane, acc);
        __syncthreads();
        if (ks + 2 < 64)
            load_stage(sb + (ks & 1) * STAGE_B, g_xh, g_xl, g_Wh, g_Wl,
                       m0, n0, HID, HID, (ks + 2) * 16, t);
        CP_COMMIT();
    }

    const int mb = m0 + wm * 64, nb = n0 + wn * 32;
#pragma unroll
    for (int mt = 0; mt < 4; ++mt)
#pragma unroll
        for (int nt = 0; nt < 4; ++nt) {
            int r0 = mb + mt * 16 + (lane >> 2);
            int c0 = nb + nt * 8 + (lane & 3) * 2;
            float b0 = g_bias[c0], b1 = g_bias[c0 + 1];
            float2 v0 = {acc[mt][nt][0] + b0, acc[mt][nt][1] + b1};
            float2 v1 = {acc[mt][nt][2] + b0, acc[mt][nt][3] + b1};
            *reinterpret_cast<float2*>(&g_proj[(size_t)r0 * NPROJ + c0]) = v0;
            *reinterpret_cast<float2*>(&g_proj[(size_t)(r0 + 8) * NPROJ + c0]) = v1;
        }
}

// ---------------------------------------------------------------- RoPE
__global__ __launch_bounds__(256) void rope_kernel(const int* __restrict__ xp,
                                                   const int* __restrict__ yp) {
    int unit = blockIdx.x * 4 + (threadIdx.x >> 6);
    int m    = unit / NHEADS;
    int head = unit - m * NHEADS;
    int t    = threadIdx.x & 63;
    int qk   = t >> 5, i = t & 31;

    float2 v = *reinterpret_cast<const float2*>(
        &g_proj[(size_t)m * NPROJ + head * 128 + qk * 64 + 2 * i]);

    int p = (i < 16) ? xp[m] : yp[m];
    int f = (i < 16) ? i : (i - 16);
    float ang = (float)p * exp2f(-0.83048202372184f * (float)f);
    float sn, cs;
    sincosf(ang, &sn, &cs);
    float rx = v.x * cs - v.y * sn;
    float ry = v.y * cs + v.x * sn;

    union { __nv_bfloat16 h[2]; uint32_t u; } H, L;
    H.h[0] = __float2bfloat16(rx); L.h[0] = __float2bfloat16(rx - __bfloat162float(H.h[0]));
    H.h[1] = __float2bfloat16(ry); L.h[1] = __float2bfloat16(ry - __bfloat162float(H.h[1]));

    int b = m >> 9, sidx = m & (SEQ - 1);
    size_t o = (((size_t)(b * NHEADS + head) * SEQ + sidx) * 64 + 2 * i) >> 1;
    if (qk == 0) { reinterpret_cast<uint32_t*>(g_qh)[o] = H.u; reinterpret_cast<uint32_t*>(g_ql)[o] = L.u; }
    else         { reinterpret_cast<uint32_t*>(g_kh)[o] = H.u; reinterpret_cast<uint32_t*>(g_kl)[o] = L.u; }
}

// ---------------------------------------------------------------- attn GEMM
__global__ __launch_bounds__(256) void attn_mma(const int* __restrict__ amask,
                                                float* __restrict__ out) {
    __shared__ __align__(128) char smem[2 * STAGE_B];
    uint32_t sb = smem_u32(smem);
    const int t = threadIdx.x, lane = t & 31, w = t >> 5;
    const int wm = w >> 2, wn = w & 3;
    const int bh = blockIdx.z;
    const int b = bh / NHEADS, head = bh - b * NHEADS;
    const int m0 = blockIdx.y * 128, n0 = blockIdx.x * 128;

    const __nv_bfloat16* Qh = g_qh + (size_t)bh * SEQ * 64;
    const __nv_bfloat16* Ql = g_ql + (size_t)bh * SEQ * 64;
    const __nv_bfloat16* Kh = g_kh + (size_t)bh * SEQ * 64;
    const __nv_bfloat16* Kl = g_kl + (size_t)bh * SEQ * 64;

    float acc[4][4][4];
#pragma unroll
    for (int i = 0; i < 4; ++i)
#pragma unroll
        for (int j = 0; j < 4; ++j)
#pragma unroll
            for (int k = 0; k < 4; ++k) acc[i][j][k] = 0.f;

    load_stage(sb,           Qh, Ql, Kh, Kl, m0, n0, 64, 64, 0, t);
    CP_COMMIT();
    load_stage(sb + STAGE_B, Qh, Ql, Kh, Kl, m0, n0, 64, 64, 16, t);
    CP_COMMIT();

#pragma unroll 1
    for (int ks = 0; ks < 4; ++ks) {
        CP_WAIT1();
        __syncthreads();
        compute_stage(sb + (ks & 1) * STAGE_B, wm, wn, lane, acc);
        __syncthreads();
        if (ks + 2 < 4)
            load_stage(sb + (ks & 1) * STAGE_B, Qh, Ql, Kh, Kl,
                       m0, n0, 64, 64, (ks + 2) * 16, t);
        CP_COMMIT();
    }

    const int* msk = amask + b * SEQ;
    const bool ent = head < 2;
    const int mb = m0 + wm * 64, nb = n0 + wn * 32;
#pragma unroll
    for (int mt = 0; mt < 4; ++mt) {
        int r0 = mb + mt * 16 + (lane >> 2);
        int r1 = r0 + 8;
        bool pm0 = msk[r0] > 0, pm1 = msk[r1] > 0;
#pragma unroll
        for (int nt = 0; nt < 4; ++nt) {
            int c0 = nb + nt * 8 + (lane & 3) * 2;
            bool pc0 = msk[c0] > 0, pc1 = msk[c0 + 1] > 0;
            float v00 = (pm0 && pc0) ? acc[mt][nt][0] : -INFINITY;
            float v01 = (pm0 && pc1) ? acc[mt][nt][1] : -INFINITY;
            float v10 = (pm1 && pc0) ? acc[mt][nt][2] : -INFINITY;
            float v11 = (pm1 && pc1) ? acc[mt][nt][3] : -INFINITY;
            if (ent) {
                if (r0 > c0)     v00 -= 1e12f;
                if (r0 > c0 + 1) v01 -= 1e12f;
                if (r1 > c0)     v10 -= 1e12f;
                if (r1 > c0 + 1) v11 -= 1e12f;
            }
            float2 o0 = {v00 * 0.125f, v01 * 0.125f};
            float2 o1 = {v10 * 0.125f, v11 * 0.125f};
            *reinterpret_cast<float2*>(&out[((size_t)bh * SEQ + r0) * SEQ + c0]) = o0;
            *reinterpret_cast<float2*>(&out[((size_t)bh * SEQ + r1) * SEQ + c0]) = o1;
        }
    }
}

// ---------------------------------------------------------------- launch
extern "C" void kernel_launch(void* const* d_in, const int* in_sizes, int n_in,
                              void* d_out, int out_size) {
    const float* x      = (const float*)d_in[0];
    const int*   amask  = (const int*)  d_in[1];
    const int*   xp     = (const int*)  d_in[2];
    const int*   yp     = (const int*)  d_in[3];
    const float* W_ent  = (const float*)d_in[4];
    const float* b_ent  = (const float*)d_in[5];
    const float* W_head = (const float*)d_in[6];
    const float* b_head = (const float*)d_in[7];
    const float* W_tail = (const float*)d_in[8];
    const float* b_tail = (const float*)d_in[9];
    float* out = (float*)d_out;

    conv_x<<<(M_TOT * HID) / (256 * 4), 256>>>(x);
    conv_w<<<dim3(256 / 32, HID / 32),  dim3(32, 32)>>>(W_ent,  256,    0);
    conv_w<<<dim3(3072 / 32, HID / 32), dim3(32, 32)>>>(W_head, 3072,  256);
    conv_w<<<dim3(3072 / 32, HID / 32), dim3(32, 32)>>>(W_tail, 3072, 3328);
    conv_b<<<(NPROJ + 255) / 256, 256>>>(b_ent, b_head, b_tail);
    proj_mma<<<dim3(NPROJ / 128, M_TOT / 128), 256>>>();
    rope_kernel<<<(M_TOT * NHEADS) / 4, 256>>>(xp, yp);
    attn_mma<<<dim3(4, 4, BSZ * NHEADS), 256>>>(amask, out);
}

// round 6
// speedup vs baseline: 5.6444x; 2.0202x over previous
#include <cuda_runtime.h>
#include <cuda_bf16.h>
#include <cstdint>
#include <math.h>

#define BSZ     4
#define SEQ     512
#define HID     1024
#define M_TOT   2048
#define NPROJ   6400
#define NHEADS  50

// ---------------------------------------------------------------- scratch
__device__ float         g_bias[NPROJ];
__device__ __nv_bfloat16 g_xb[(size_t)M_TOT * HID];      // bf16 x
__device__ __nv_bfloat16 g_Wb[(size_t)NPROJ * HID];      // bf16 W, [n][k]
__device__ __nv_bfloat16 g_qk[(size_t)M_TOT * NPROJ];    // rotated q/k, [m][6400]

// ---------------------------------------------------------------- helpers
__device__ __forceinline__ uint32_t smem_u32(const void* p) {
    uint32_t a;
    asm("{ .reg .u64 t; cvta.to.shared.u64 t, %1; cvt.u32.u64 %0, t; }" : "=r"(a) : "l"(p));
    return a;
}
__device__ __forceinline__ void cp16(uint32_t dst, const void* src) {
    asm volatile("cp.async.cg.shared.global [%0], [%1], 16;" :: "r"(dst), "l"(src));
}
#define CP_COMMIT() asm volatile("cp.async.commit_group;" ::: "memory")
#define CP_WAIT1()  asm volatile("cp.async.wait_group 1;" ::: "memory")
#define CP_WAIT0()  asm volatile("cp.async.wait_group 0;" ::: "memory")

__device__ __forceinline__ void ldsm4(uint32_t* r, uint32_t a) {
    asm volatile("ldmatrix.sync.aligned.m8n8.x4.shared.b16 {%0,%1,%2,%3}, [%4];"
                 : "=r"(r[0]), "=r"(r[1]), "=r"(r[2]), "=r"(r[3]) : "r"(a));
}
__device__ __forceinline__ void mma16816(float* d, const uint32_t* a, const uint32_t* b) {
    asm volatile("mma.sync.aligned.m16n8k16.row.col.f32.bf16.bf16.f32 "
                 "{%0,%1,%2,%3}, {%4,%5,%6,%7}, {%8,%9}, {%0,%1,%2,%3};"
                 : "+f"(d[0]), "+f"(d[1]), "+f"(d[2]), "+f"(d[3])
                 : "r"(a[0]), "r"(a[1]), "r"(a[2]), "r"(a[3]), "r"(b[0]), "r"(b[1]));
}

// proj smem tile: 128 rows x 16 bf16 (32B) + 16B pad = 48B stride
#define TSTRIDE 48
#define TILE_B  (128 * TSTRIDE)      // 6144
#define STAGE_B (2 * TILE_B)         // A + B

// ---------------------------------------------------------------- conversions
__global__ __launch_bounds__(256) void conv_x(const float* __restrict__ x) {
    int i = blockIdx.x * 256 + threadIdx.x;          // 4 floats per thread
    float4 v = reinterpret_cast<const float4*>(x)[i];
    union { __nv_bfloat16 h[4]; uint2 u; } H;
    H.h[0] = __float2bfloat16(v.x); H.h[1] = __float2bfloat16(v.y);
    H.h[2] = __float2bfloat16(v.z); H.h[3] = __float2bfloat16(v.w);
    reinterpret_cast<uint2*>(g_xb)[i] = H.u;
}

__global__ __launch_bounds__(1024) void conv_w(const float* __restrict__ W, int Nsec, int colOff) {
    __shared__ float tile[32][33];
    int n0 = blockIdx.x * 32, k0 = blockIdx.y * 32;
    int tx = threadIdx.x, ty = threadIdx.y;
    tile[ty][tx] = W[(size_t)(k0 + ty) * Nsec + n0 + tx];
    __syncthreads();
    g_Wb[(size_t)(colOff + n0 + ty) * HID + k0 + tx] = __float2bfloat16(tile[tx][ty]);
}

__global__ void conv_b(const float* __restrict__ be, const float* __restrict__ bh,
                       const float* __restrict__ bt) {
    int i = blockIdx.x * 256 + threadIdx.x;
    if (i < NPROJ)
        g_bias[i] = (i < 256) ? be[i] : (i < 3328) ? bh[i - 256] : bt[i - 3328];
}

// ---------------------------------------------------------------- proj GEMM + fused RoPE
// qk[2048,6400] = rope( xb @ Wb^T + bias ).  Tile 128x128, BK=16, 2-stage cp.async.
__global__ __launch_bounds__(256) void proj_mma(const int* __restrict__ xp,
                                                const int* __restrict__ yp) {
    __shared__ __align__(128) char smem[2 * STAGE_B];    // 24576
    uint32_t sb = smem_u32(smem);
    const int t = threadIdx.x, lane = t & 31, w = t >> 5;
    const int wm = w >> 2, wn = w & 3;
    const int n0 = blockIdx.x * 128, m0 = blockIdx.y * 128;

    float acc[4][4][4];
#pragma unroll
    for (int i = 0; i < 4; ++i)
#pragma unroll
        for (int j = 0; j < 4; ++j)
#pragma unroll
            for (int k = 0; k < 4; ++k) acc[i][j][k] = 0.f;

    // stage loader: thread -> one 16B chunk of A tile + one of B tile
    const int row = t >> 1, half = t & 1;
#pragma unroll 1
    for (int pre = 0; pre < 2; ++pre) {
        uint32_t d = sb + pre * STAGE_B + row * TSTRIDE + half * 16;
        int k0 = pre * 16;
        cp16(d,          g_xb + (size_t)(m0 + row) * HID + k0 + half * 8);
        cp16(d + TILE_B, g_Wb + (size_t)(n0 + row) * HID + k0 + half * 8);
        CP_COMMIT();
    }

#pragma unroll 1
    for (int ks = 0; ks < 64; ++ks) {
        CP_WAIT1();
        __syncthreads();
        {
            uint32_t s = sb + (ks & 1) * STAGE_B;
            uint32_t A[4][4], B[2][4];
            uint32_t aoff = (uint32_t)((wm * 64 + (lane & 15)) * TSTRIDE + ((lane >> 4) & 1) * 16);
#pragma unroll
            for (int mt = 0; mt < 4; ++mt) ldsm4(A[mt], s + mt * 16 * TSTRIDE + aoff);
            uint32_t boff = (uint32_t)((wn * 32 + (lane & 7) + ((lane >> 4) & 1) * 8) * TSTRIDE
                                       + ((lane >> 3) & 1) * 16);
#pragma unroll
            for (int np = 0; np < 2; ++np) ldsm4(B[np], s + TILE_B + np * 16 * TSTRIDE + boff);
#pragma unroll
            for (int mt = 0; mt < 4; ++mt)
#pragma unroll
                for (int nt = 0; nt < 4; ++nt)
                    mma16816(acc[mt][nt], A[mt], &B[nt >> 1][(nt & 1) * 2]);
        }
        __syncthreads();
        if (ks + 2 < 64) {
            uint32_t d = sb + (ks & 1) * STAGE_B + row * TSTRIDE + half * 16;
            int k0 = (ks + 2) * 16;
            cp16(d,          g_xb + (size_t)(m0 + row) * HID + k0 + half * 8);
            cp16(d + TILE_B, g_Wb + (size_t)(n0 + row) * HID + k0 + half * 8);
        }
        CP_COMMIT();
    }

    // ---- epilogue: bias + RoPE rotate + bf16 store ----
    // column pair (c0, c0+1), c0 even -> one rotation pair. d = col within 64.
    const int dbase = (wn & 1) * 32;
    float bias0[4], bias1[4], efac[4];
    int   selx[4], dloc[4];
#pragma unroll
    for (int nt = 0; nt < 4; ++nt) {
        int c0 = n0 + wn * 32 + nt * 8 + (lane & 3) * 2;
        bias0[nt] = g_bias[c0];
        bias1[nt] = g_bias[c0 + 1];
        int d = dbase + nt * 8 + (lane & 3) * 2;
        int i = d >> 1;
        int f = (i < 16) ? i : i - 16;
        selx[nt] = (i < 16);
        efac[nt] = exp2f(-0.83048202372184f * (float)f);
        dloc[nt] = c0;
    }
    const int mb = m0 + wm * 64;
#pragma unroll
    for (int mt = 0; mt < 4; ++mt) {
#pragma unroll
        for (int rr = 0; rr < 2; ++rr) {
            int m = mb + mt * 16 + (lane >> 2) + rr * 8;
            int px = xp[m], py = yp[m];
            __nv_bfloat16* drow = g_qk + (size_t)m * NPROJ;
#pragma unroll
            for (int nt = 0; nt < 4; ++nt) {
                float p = (float)(selx[nt] ? px : py);
                float sn, cs;
                __sincosf(p * efac[nt], &sn, &cs);
                float v0 = acc[mt][nt][rr * 2 + 0] + bias0[nt];
                float v1 = acc[mt][nt][rr * 2 + 1] + bias1[nt];
                union { __nv_bfloat16 h[2]; uint32_t u; } o;
                o.h[0] = __float2bfloat16(v0 * cs - v1 * sn);
                o.h[1] = __float2bfloat16(v1 * cs + v0 * sn);
                *reinterpret_cast<uint32_t*>(drow + dloc[nt]) = o.u;
            }
        }
    }
}

// ---------------------------------------------------------------- attn GEMM
// S = Q @ K^T per (b, head); Q/K slices of g_qk. Full K=64 in one smem stage.
#define ASTRIDE 144
#define ATILE_B (128 * ASTRIDE)      // 18432

__global__ __launch_bounds__(256) void attn_mma(const int* __restrict__ amask,
                                                float* __restrict__ out) {
    __shared__ __align__(128) char smem[2 * ATILE_B];    // 36864
    uint32_t sb = smem_u32(smem);
    const int t = threadIdx.x, lane = t & 31, w = t >> 5;
    const int wm = w >> 2, wn = w & 3;
    const int bh = blockIdx.z;
    const int b = bh / NHEADS, head = bh - b * NHEADS;
    const int m0 = blockIdx.y * 128, n0 = blockIdx.x * 128;

    const __nv_bfloat16* Qg = g_qk + (size_t)(b * SEQ) * NPROJ + head * 128;
    const __nv_bfloat16* Kg = Qg + 64;

    // load Q tile (rows m0..m0+127, 64 bf16) and K tile (rows n0..)
#pragma unroll
    for (int i = 0; i < 4; ++i) {
        int idx = i * 256 + t;                 // 0..1023
        int r = idx >> 3, c = idx & 7;         // 16B units within 128B row
        cp16(sb + r * ASTRIDE + c * 16,           Qg + (size_t)(m0 + r) * NPROJ + c * 8);
        cp16(sb + ATILE_B + r * ASTRIDE + c * 16, Kg + (size_t)(n0 + r) * NPROJ + c * 8);
    }
    CP_COMMIT();

    float acc[4][4][4];
#pragma unroll
    for (int i = 0; i < 4; ++i)
#pragma unroll
        for (int j = 0; j < 4; ++j)
#pragma unroll
            for (int k = 0; k < 4; ++k) acc[i][j][k] = 0.f;

    CP_WAIT0();
    __syncthreads();

#pragma unroll
    for (int ks = 0; ks < 4; ++ks) {
        uint32_t A[4][4], B[2][4];
        uint32_t aoff = (uint32_t)((wm * 64 + (lane & 15)) * ASTRIDE + ks * 32
                                   + ((lane >> 4) & 1) * 16);
#pragma unroll
        for (int mt = 0; mt < 4; ++mt) ldsm4(A[mt], sb + mt * 16 * ASTRIDE + aoff);
        uint32_t boff = (uint32_t)((wn * 32 + (lane & 7) + ((lane >> 4) & 1) * 8) * ASTRIDE
                                   + ks * 32 + ((lane >> 3) & 1) * 16);
#pragma unroll
        for (int np = 0; np < 2; ++np) ldsm4(B[np], sb + ATILE_B + np * 16 * ASTRIDE + boff);
#pragma unroll
        for (int mt = 0; mt < 4; ++mt)
#pragma unroll
            for (int nt = 0; nt < 4; ++nt)
                mma16816(acc[mt][nt], A[mt], &B[nt >> 1][(nt & 1) * 2]);
    }

    const int* msk = amask + b * SEQ;
    const bool ent = head < 2;
    const int mb = m0 + wm * 64, nb = n0 + wn * 32;
#pragma unroll
    for (int mt = 0; mt < 4; ++mt) {
        int r0 = mb + mt * 16 + (lane >> 2);
        int r1 = r0 + 8;
        bool pm0 = msk[r0] > 0, pm1 = msk[r1] > 0;
#pragma unroll
        for (int nt = 0; nt < 4; ++nt) {
            int c0 = nb + nt * 8 + (lane & 3) * 2;
            bool pc0 = msk[c0] > 0, pc1 = msk[c0 + 1] > 0;
            float v00 = (pm0 && pc0) ? acc[mt][nt][0] : -INFINITY;
            float v01 = (pm0 && pc1) ? acc[mt][nt][1] : -INFINITY;
            float v10 = (pm1 && pc0) ? acc[mt][nt][2] : -INFINITY;
            float v11 = (pm1 && pc1) ? acc[mt][nt][3] : -INFINITY;
            if (ent) {
                if (r0 > c0)     v00 -= 1e12f;
                if (r0 > c0 + 1) v01 -= 1e12f;
                if (r1 > c0)     v10 -= 1e12f;
                if (r1 > c0 + 1) v11 -= 1e12f;
            }
            float2 o0 = {v00 * 0.125f, v01 * 0.125f};
            float2 o1 = {v10 * 0.125f, v11 * 0.125f};
            *reinterpret_cast<float2*>(&out[((size_t)bh * SEQ + r0) * SEQ + c0]) = o0;
            *reinterpret_cast<float2*>(&out[((size_t)bh * SEQ + r1) * SEQ + c0]) = o1;
        }
    }
}

// ---------------------------------------------------------------- launch
extern "C" void kernel_launch(void* const* d_in, const int* in_sizes, int n_in,
                              void* d_out, int out_size) {
    const float* x      = (const float*)d_in[0];
    const int*   amask  = (const int*)  d_in[1];
    const int*   xp     = (const int*)  d_in[2];
    const int*   yp     = (const int*)  d_in[3];
    const float* W_ent  = (const float*)d_in[4];
    const float* b_ent  = (const float*)d_in[5];
    const float* W_head = (const float*)d_in[6];
    const float* b_head = (const float*)d_in[7];
    const float* W_tail = (const float*)d_in[8];
    const float* b_tail = (const float*)d_in[9];
    float* out = (float*)d_out;

    conv_x<<<(M_TOT * HID) / (256 * 4), 256>>>(x);
    conv_w<<<dim3(256 / 32, HID / 32),  dim3(32, 32)>>>(W_ent,  256,    0);
    conv_w<<<dim3(3072 / 32, HID / 32), dim3(32, 32)>>>(W_head, 3072,  256);
    conv_w<<<dim3(3072 / 32, HID / 32), dim3(32, 32)>>>(W_tail, 3072, 3328);
    conv_b<<<(NPROJ + 255) / 256, 256>>>(b_ent, b_head, b_tail);
    proj_mma<<<dim3(NPROJ / 128, M_TOT / 128), 256>>>(xp, yp);
    attn_mma<<<dim3(4, 4, BSZ * NHEADS), 256>>>(amask, out);
}

// round 7
// speedup vs baseline: 6.8720x; 1.2175x over previous
#include <cuda_runtime.h>
#include <cuda_bf16.h>
#include <cstdint>
#include <math.h>

#define BSZ     4
#define SEQ     512
#define HID     1024
#define M_TOT   2048
#define NPROJ   6400
#define NHEADS  50

// ---------------------------------------------------------------- scratch
__device__ float         g_bias[NPROJ];
__device__ __nv_bfloat16 g_xb[(size_t)M_TOT * HID];      // bf16 x, [m][k]
__device__ __nv_bfloat16 g_Wb[(size_t)HID * NPROJ];      // bf16 W, [k][n] (native)
__device__ __nv_bfloat16 g_qk[(size_t)M_TOT * NPROJ];    // rotated q/k, [m][6400]

// ---------------------------------------------------------------- helpers
__device__ __forceinline__ uint32_t smem_u32(const void* p) {
    uint32_t a;
    asm("{ .reg .u64 t; cvta.to.shared.u64 t, %1; cvt.u32.u64 %0, t; }" : "=r"(a) : "l"(p));
    return a;
}
__device__ __forceinline__ void cp16(uint32_t dst, const void* src) {
    asm volatile("cp.async.cg.shared.global [%0], [%1], 16;" :: "r"(dst), "l"(src));
}
#define CP_COMMIT() asm volatile("cp.async.commit_group;" ::: "memory")
#define CP_WAIT1()  asm volatile("cp.async.wait_group 1;" ::: "memory")
#define CP_WAIT0()  asm volatile("cp.async.wait_group 0;" ::: "memory")

__device__ __forceinline__ void ldsm4(uint32_t* r, uint32_t a) {
    asm volatile("ldmatrix.sync.aligned.m8n8.x4.shared.b16 {%0,%1,%2,%3}, [%4];"
                 : "=r"(r[0]), "=r"(r[1]), "=r"(r[2]), "=r"(r[3]) : "r"(a));
}
__device__ __forceinline__ void ldsm4t(uint32_t* r, uint32_t a) {
    asm volatile("ldmatrix.sync.aligned.m8n8.x4.trans.shared.b16 {%0,%1,%2,%3}, [%4];"
                 : "=r"(r[0]), "=r"(r[1]), "=r"(r[2]), "=r"(r[3]) : "r"(a));
}
__device__ __forceinline__ void mma16816(float* d, const uint32_t* a, const uint32_t* b) {
    asm volatile("mma.sync.aligned.m16n8k16.row.col.f32.bf16.bf16.f32 "
                 "{%0,%1,%2,%3}, {%4,%5,%6,%7}, {%8,%9}, {%0,%1,%2,%3};"
                 : "+f"(d[0]), "+f"(d[1]), "+f"(d[2]), "+f"(d[3])
                 : "r"(a[0]), "r"(a[1]), "r"(a[2]), "r"(a[3]), "r"(b[0]), "r"(b[1]));
}

// ---------------------------------------------------------------- conversions
__global__ __launch_bounds__(256) void conv_x(const float* __restrict__ x) {
    int i = blockIdx.x * 256 + threadIdx.x;
    float4 v = reinterpret_cast<const float4*>(x)[i];
    union { __nv_bfloat16 h[4]; uint2 u; } H;
    H.h[0] = __float2bfloat16(v.x); H.h[1] = __float2bfloat16(v.y);
    H.h[2] = __float2bfloat16(v.z); H.h[3] = __float2bfloat16(v.w);
    reinterpret_cast<uint2*>(g_xb)[i] = H.u;
}

// fused W conversion, no transpose: g_Wb[k][n], n in [0,6400)
__global__ __launch_bounds__(256) void conv_w_all(const float* __restrict__ We,
                                                  const float* __restrict__ Wh,
                                                  const float* __restrict__ Wt) {
    int idx = blockIdx.x * 256 + threadIdx.x;      // over 1024*1600
    int k = idx / 1600, n = (idx - k * 1600) * 4;
    const float* src; int nn, ld;
    if (n < 256)       { src = We; nn = n;        ld = 256;  }
    else if (n < 3328) { src = Wh; nn = n - 256;  ld = 3072; }
    else               { src = Wt; nn = n - 3328; ld = 3072; }
    float4 v = *reinterpret_cast<const float4*>(src + (size_t)k * ld + nn);
    union { __nv_bfloat16 h[4]; uint2 u; } H;
    H.h[0] = __float2bfloat16(v.x); H.h[1] = __float2bfloat16(v.y);
    H.h[2] = __float2bfloat16(v.z); H.h[3] = __float2bfloat16(v.w);
    *reinterpret_cast<uint2*>(g_Wb + (size_t)k * NPROJ + n) = H.u;
}

__global__ void conv_b(const float* __restrict__ be, const float* __restrict__ bh,
                       const float* __restrict__ bt) {
    int i = blockIdx.x * 256 + threadIdx.x;
    if (i < NPROJ)
        g_bias[i] = (i < 256) ? be[i] : (i < 3328) ? bh[i - 256] : bt[i - 3328];
}

// ---------------------------------------------------------------- proj GEMM + fused RoPE
// qk[2048,6400] = rope( xb @ Wb + bias ). Tile 128x128, BK=32, 2-stage cp.async.
// A smem: [m][k] 128 rows x 64B (+16 pad = 80B stride). ldmatrix non-trans.
// B smem: [k][n] 32 rows x 256B (+16 pad = 272B stride). ldmatrix.trans.
#define BK    32
#define ASTR  80
#define BSTR  272
#define A_B   (128 * ASTR)          // 10240
#define B_B   (BK * BSTR)           // 8704
#define STG   (A_B + B_B)           // 18944

__global__ __launch_bounds__(256) void proj_mma(const int* __restrict__ xp,
                                                const int* __restrict__ yp) {
    __shared__ __align__(128) char smem[2 * STG];       // 37888
    uint32_t sb = smem_u32(smem);
    const int t = threadIdx.x, lane = t & 31, w = t >> 5;
    const int wm = w >> 2, wn = w & 3;
    const int n0 = blockIdx.x * 128, m0 = blockIdx.y * 128;

    float acc[4][4][4];
#pragma unroll
    for (int i = 0; i < 4; ++i)
#pragma unroll
        for (int j = 0; j < 4; ++j)
#pragma unroll
            for (int k = 0; k < 4; ++k) acc[i][j][k] = 0.f;

    // prefetch 2 stages
#pragma unroll
    for (int pre = 0; pre < 2; ++pre) {
        uint32_t s = sb + pre * STG;
        int k0 = pre * BK;
#pragma unroll
        for (int i = 0; i < 2; ++i) {   // A: 512 16B chunks
            int id = i * 256 + t, r = id >> 2, c = id & 3;
            cp16(s + r * ASTR + c * 16, g_xb + (size_t)(m0 + r) * HID + k0 + c * 8);
        }
#pragma unroll
        for (int i = 0; i < 2; ++i) {   // B: 32 rows x 16 chunks
            int id = i * 256 + t, r = id >> 4, c = id & 15;
            cp16(s + A_B + r * BSTR + c * 16, g_Wb + (size_t)(k0 + r) * NPROJ + n0 + c * 8);
        }
        CP_COMMIT();
    }

    // B ldmatrix.trans address: groups of 8 lanes -> (k-subrow, n-subcol) quadrants
    const int bg = lane >> 3, br = lane & 7;
    const uint32_t bq = (uint32_t)(((bg & 1) * 8 + br) * BSTR + ((bg >> 1) * 8 + wn * 32) * 2);
    const uint32_t aoff = (uint32_t)((wm * 64 + (lane & 15)) * ASTR + ((lane >> 4) & 1) * 16);

#pragma unroll 1
    for (int ks = 0; ks < 32; ++ks) {
        CP_WAIT1();
        __syncthreads();
        uint32_t s = sb + (ks & 1) * STG;
#pragma unroll
        for (int kk = 0; kk < 2; ++kk) {
            uint32_t A[4][4], B[2][4];
#pragma unroll
            for (int mt = 0; mt < 4; ++mt)
                ldsm4(A[mt], s + mt * 16 * ASTR + aoff + kk * 32);
#pragma unroll
            for (int np = 0; np < 2; ++np)
                ldsm4t(B[np], s + A_B + kk * 16 * BSTR + bq + np * 32);
#pragma unroll
            for (int mt = 0; mt < 4; ++mt)
#pragma unroll
                for (int nt = 0; nt < 4; ++nt)
                    mma16816(acc[mt][nt], A[mt], &B[nt >> 1][(nt & 1) * 2]);
        }
        __syncthreads();
        if (ks + 2 < 32) {
            int k0 = (ks + 2) * BK;
#pragma unroll
            for (int i = 0; i < 2; ++i) {
                int id = i * 256 + t, r = id >> 2, c = id & 3;
                cp16(s + r * ASTR + c * 16, g_xb + (size_t)(m0 + r) * HID + k0 + c * 8);
            }
#pragma unroll
            for (int i = 0; i < 2; ++i) {
                int id = i * 256 + t, r = id >> 4, c = id & 15;
                cp16(s + A_B + r * BSTR + c * 16, g_Wb + (size_t)(k0 + r) * NPROJ + n0 + c * 8);
            }
        }
        CP_COMMIT();
    }

    // ---- epilogue: bias + RoPE rotate + bf16 store ----
    const int dbase = (wn & 1) * 32;
    float bias0[4], bias1[4], efac[4];
    int   selx[4], dloc[4];
#pragma unroll
    for (int nt = 0; nt < 4; ++nt) {
        int c0 = n0 + wn * 32 + nt * 8 + (lane & 3) * 2;
        bias0[nt] = g_bias[c0];
        bias1[nt] = g_bias[c0 + 1];
        int d = dbase + nt * 8 + (lane & 3) * 2;
        int i = d >> 1;
        int f = (i < 16) ? i : i - 16;
        selx[nt] = (i < 16);
        efac[nt] = exp2f(-0.83048202372184f * (float)f);
        dloc[nt] = c0;
    }
    const int mb = m0 + wm * 64;
#pragma unroll
    for (int mt = 0; mt < 4; ++mt) {
#pragma unroll
        for (int rr = 0; rr < 2; ++rr) {
            int m = mb + mt * 16 + (lane >> 2) + rr * 8;
            int px = xp[m], py = yp[m];
            __nv_bfloat16* drow = g_qk + (size_t)m * NPROJ;
#pragma unroll
            for (int nt = 0; nt < 4; ++nt) {
                float p = (float)(selx[nt] ? px : py);
                float sn, cs;
                __sincosf(p * efac[nt], &sn, &cs);
                float v0 = acc[mt][nt][rr * 2 + 0] + bias0[nt];
                float v1 = acc[mt][nt][rr * 2 + 1] + bias1[nt];
                union { __nv_bfloat16 h[2]; uint32_t u; } o;
                o.h[0] = __float2bfloat16(v0 * cs - v1 * sn);
                o.h[1] = __float2bfloat16(v1 * cs + v0 * sn);
                *reinterpret_cast<uint32_t*>(drow + dloc[nt]) = o.u;
            }
        }
    }
}

// ---------------------------------------------------------------- attn GEMM
#define ASTRIDE 144
#define ATILE_B (128 * ASTRIDE)      // 18432

__global__ __launch_bounds__(256) void attn_mma(const int* __restrict__ amask,
                                                float* __restrict__ out) {
    __shared__ __align__(128) char smem[2 * ATILE_B];    // 36864
    uint32_t sb = smem_u32(smem);
    const int t = threadIdx.x, lane = t & 31, w = t >> 5;
    const int wm = w >> 2, wn = w & 3;
    const int bh = blockIdx.z;
    const int b = bh / NHEADS, head = bh - b * NHEADS;
    const int m0 = blockIdx.y * 128, n0 = blockIdx.x * 128;

    const __nv_bfloat16* Qg = g_qk + (size_t)(b * SEQ) * NPROJ + head * 128;
    const __nv_bfloat16* Kg = Qg + 64;

#pragma unroll
    for (int i = 0; i < 4; ++i) {
        int idx = i * 256 + t;
        int r = idx >> 3, c = idx & 7;
        cp16(sb + r * ASTRIDE + c * 16,           Qg + (size_t)(m0 + r) * NPROJ + c * 8);
        cp16(sb + ATILE_B + r * ASTRIDE + c * 16, Kg + (size_t)(n0 + r) * NPROJ + c * 8);
    }
    CP_COMMIT();

    float acc[4][4][4];
#pragma unroll
    for (int i = 0; i < 4; ++i)
#pragma unroll
        for (int j = 0; j < 4; ++j)
#pragma unroll
            for (int k = 0; k < 4; ++k) acc[i][j][k] = 0.f;

    CP_WAIT0();
    __syncthreads();

#pragma unroll
    for (int ks = 0; ks < 4; ++ks) {
        uint32_t A[4][4], B[2][4];
        uint32_t aoff = (uint32_t)((wm * 64 + (lane & 15)) * ASTRIDE + ks * 32
                                   + ((lane >> 4) & 1) * 16);
#pragma unroll
        for (int mt = 0; mt < 4; ++mt) ldsm4(A[mt], sb + mt * 16 * ASTRIDE + aoff);
        uint32_t boff = (uint32_t)((wn * 32 + (lane & 7) + ((lane >> 4) & 1) * 8) * ASTRIDE
                                   + ks * 32 + ((lane >> 3) & 1) * 16);
#pragma unroll
        for (int np = 0; np < 2; ++np) ldsm4(B[np], sb + ATILE_B + np * 16 * ASTRIDE + boff);
#pragma unroll
        for (int mt = 0; mt < 4; ++mt)
#pragma unroll
            for (int nt = 0; nt < 4; ++nt)
                mma16816(acc[mt][nt], A[mt], &B[nt >> 1][(nt & 1) * 2]);
    }

    const int* msk = amask + b * SEQ;
    const bool ent = head < 2;
    const int mb = m0 + wm * 64, nb = n0 + wn * 32;
#pragma unroll
    for (int mt = 0; mt < 4; ++mt) {
        int r0 = mb + mt * 16 + (lane >> 2);
        int r1 = r0 + 8;
        bool pm0 = msk[r0] > 0, pm1 = msk[r1] > 0;
#pragma unroll
        for (int nt = 0; nt < 4; ++nt) {
            int c0 = nb + nt * 8 + (lane & 3) * 2;
            bool pc0 = msk[c0] > 0, pc1 = msk[c0 + 1] > 0;
            float v00 = (pm0 && pc0) ? acc[mt][nt][0] : -INFINITY;
            float v01 = (pm0 && pc1) ? acc[mt][nt][1] : -INFINITY;
            float v10 = (pm1 && pc0) ? acc[mt][nt][2] : -INFINITY;
            float v11 = (pm1 && pc1) ? acc[mt][nt][3] : -INFINITY;
            if (ent) {
                if (r0 > c0)     v00 -= 1e12f;
                if (r0 > c0 + 1) v01 -= 1e12f;
                if (r1 > c0)     v10 -= 1e12f;
                if (r1 > c0 + 1) v11 -= 1e12f;
            }
            float2 o0 = {v00 * 0.125f, v01 * 0.125f};
            float2 o1 = {v10 * 0.125f, v11 * 0.125f};
            *reinterpret_cast<float2*>(&out[((size_t)bh * SEQ + r0) * SEQ + c0]) = o0;
            *reinterpret_cast<float2*>(&out[((size_t)bh * SEQ + r1) * SEQ + c0]) = o1;
        }
    }
}

// ---------------------------------------------------------------- launch
extern "C" void kernel_launch(void* const* d_in, const int* in_sizes, int n_in,
                              void* d_out, int out_size) {
    const float* x      = (const float*)d_in[0];
    const int*   amask  = (const int*)  d_in[1];
    const int*   xp     = (const int*)  d_in[2];
    const int*   yp     = (const int*)  d_in[3];
    const float* W_ent  = (const float*)d_in[4];
    const float* b_ent  = (const float*)d_in[5];
    const float* W_head = (const float*)d_in[6];
    const float* b_head = (const float*)d_in[7];
    const float* W_tail = (const float*)d_in[8];
    const float* b_tail = (const float*)d_in[9];
    float* out = (float*)d_out;

    conv_x<<<(M_TOT * HID) / (256 * 4), 256>>>(x);
    conv_w_all<<<(HID * (NPROJ / 4)) / 256, 256>>>(W_ent, W_head, W_tail);
    conv_b<<<(NPROJ + 255) / 256, 256>>>(b_ent, b_head, b_tail);
    proj_mma<<<dim3(NPROJ / 128, M_TOT / 128), 256>>>(xp, yp);
    attn_mma<<<dim3(4, 4, BSZ * NHEADS), 256>>>(amask, out);
}